// round 2
// baseline (speedup 1.0000x reference)
#include <cuda_runtime.h>
#include <cuda_bf16.h>
#include <math.h>

#define N_NODES 50000
#define IN_F    256
#define OUT_F   128
#define ALPHA   0.2f
#define EPSV    1e-9f

// ---------------- scratch (device globals; no allocations allowed) ----------
__device__ float g_h[(size_t)N_NODES * OUT_F];
__device__ float g_agg[(size_t)N_NODES * OUT_F];
__device__ float g_ssrc[N_NODES];
__device__ float g_sdst[N_NODES];
__device__ float g_rowsum[N_NODES];

// ---------------- GEMM: h = x @ W  (M=N_NODES, K=256, N=128) ----------------
// BM=64, BN=128, BK=16, 256 threads, 4x8 micro-tile per thread.
#define BM 64
#define BN 128
#define BK 16

__global__ __launch_bounds__(256) void gemm_kernel(
    const float* __restrict__ x, const float* __restrict__ W,
    float* __restrict__ h, int N)
{
    __shared__ float As[BK][BM + 1];   // +1 pad: conflict-free store
    __shared__ float Ws[BK][BN];

    const int tid = threadIdx.x;
    const int ty = tid >> 4;          // 0..15 (row group)
    const int tx = tid & 15;          // 0..15 (col group)
    const int block_row = blockIdx.x * BM;

    float acc[4][8];
#pragma unroll
    for (int i = 0; i < 4; i++)
#pragma unroll
        for (int j = 0; j < 8; j++) acc[i][j] = 0.f;

    const int lm = tid >> 2;          // 0..63 row for A load
    const int lk = (tid & 3) * 4;     // 0,4,8,12

    for (int k0 = 0; k0 < IN_F; k0 += BK) {
        // A tile: 64x16, one float4 per thread
        float4 av = make_float4(0.f, 0.f, 0.f, 0.f);
        const int grow = block_row + lm;
        if (grow < N)
            av = *reinterpret_cast<const float4*>(x + (size_t)grow * IN_F + k0 + lk);
        As[lk + 0][lm] = av.x; As[lk + 1][lm] = av.y;
        As[lk + 2][lm] = av.z; As[lk + 3][lm] = av.w;

        // W tile: 16x128 = 512 float4, 2 per thread, coalesced
#pragma unroll
        for (int i = 0; i < 2; i++) {
            const int idx = tid + i * 256;      // float4 index
            const int wk = idx >> 5;            // row (128/4 = 32 float4 per row)
            const int wn = (idx & 31) * 4;
            *reinterpret_cast<float4*>(&Ws[wk][wn]) =
                *reinterpret_cast<const float4*>(W + (size_t)(k0 + wk) * BN + wn);
        }
        __syncthreads();

#pragma unroll
        for (int k = 0; k < BK; k++) {
            float af[4];
#pragma unroll
            for (int i = 0; i < 4; i++) af[i] = As[k][ty * 4 + i];
            const float4 b0 = *reinterpret_cast<const float4*>(&Ws[k][tx * 8]);
            const float4 b1 = *reinterpret_cast<const float4*>(&Ws[k][tx * 8 + 4]);
            const float bf[8] = { b0.x, b0.y, b0.z, b0.w, b1.x, b1.y, b1.z, b1.w };
#pragma unroll
            for (int i = 0; i < 4; i++)
#pragma unroll
                for (int j = 0; j < 8; j++)
                    acc[i][j] = fmaf(af[i], bf[j], acc[i][j]);
        }
        __syncthreads();
    }

#pragma unroll
    for (int i = 0; i < 4; i++) {
        const int grow = block_row + ty * 4 + i;
        if (grow < N) {
            float4 v0 = make_float4(acc[i][0], acc[i][1], acc[i][2], acc[i][3]);
            float4 v1 = make_float4(acc[i][4], acc[i][5], acc[i][6], acc[i][7]);
            *reinterpret_cast<float4*>(h + (size_t)grow * OUT_F + tx * 8)     = v0;
            *reinterpret_cast<float4*>(h + (size_t)grow * OUT_F + tx * 8 + 4) = v1;
        }
    }
}

// ---------------- per-node scores: s_src[n] = h[n].a[:F], s_dst = h[n].a[F:] -
__global__ __launch_bounds__(256) void score_kernel(
    const float* __restrict__ h, const float* __restrict__ a,
    float* __restrict__ ssrc, float* __restrict__ sdst, int N)
{
    const int warp = (blockIdx.x * blockDim.x + threadIdx.x) >> 5;
    const int lane = threadIdx.x & 31;
    if (warp >= N) return;

    const float4 hv = reinterpret_cast<const float4*>(h + (size_t)warp * OUT_F)[lane];
    const float4 as = reinterpret_cast<const float4*>(a)[lane];
    const float4 ad = reinterpret_cast<const float4*>(a + OUT_F)[lane];

    float s1 = hv.x * as.x + hv.y * as.y + hv.z * as.z + hv.w * as.w;
    float s2 = hv.x * ad.x + hv.y * ad.y + hv.z * ad.z + hv.w * ad.w;
#pragma unroll
    for (int o = 16; o > 0; o >>= 1) {
        s1 += __shfl_xor_sync(0xFFFFFFFFu, s1, o);
        s2 += __shfl_xor_sync(0xFFFFFFFFu, s2, o);
    }
    if (lane == 0) { ssrc[warp] = s1; sdst[warp] = s2; }
}

// ---------------- edge scatter: warp per edge ---------------------------------
__device__ __forceinline__ void red_add_v4(float* addr, float4 v) {
    asm volatile("red.global.add.v4.f32 [%0], {%1, %2, %3, %4};"
                 :: "l"(addr), "f"(v.x), "f"(v.y), "f"(v.z), "f"(v.w)
                 : "memory");
}

__global__ __launch_bounds__(256) void edge_kernel(
    const int* __restrict__ src, const int* __restrict__ dst,
    const float* __restrict__ h,
    const float* __restrict__ ssrc, const float* __restrict__ sdst,
    float* __restrict__ agg, float* __restrict__ rowsum, int E)
{
    const int e = (int)((blockIdx.x * (unsigned)blockDim.x + threadIdx.x) >> 5);
    if (e >= E) return;
    const int lane = threadIdx.x & 31;

    const int s = src[e];
    const int d = dst[e];

    const float score = ssrc[s] + sdst[d];
    const float lr = score >= 0.f ? score : ALPHA * score;
    const float w = __expf(-lr);

    if (lane == 0) atomicAdd(&rowsum[s], w);

    const float4 hv = reinterpret_cast<const float4*>(h + (size_t)d * OUT_F)[lane];
    const float4 out = make_float4(hv.x * w, hv.y * w, hv.z * w, hv.w * w);
    red_add_v4(agg + (size_t)s * OUT_F + lane * 4, out);
}

// ---------------- finalize: out = elu(agg / (rowsum + eps)) -------------------
__global__ __launch_bounds__(256) void finalize_kernel(
    const float* __restrict__ agg, const float* __restrict__ rowsum,
    float* __restrict__ out, int total)
{
    const int i = blockIdx.x * blockDim.x + threadIdx.x;
    if (i >= total) return;
    const float v = agg[i] / (rowsum[i >> 7] + EPSV);
    out[i] = v > 0.f ? v : expm1f(v);
}

// ---------------- launch ------------------------------------------------------
extern "C" void kernel_launch(void* const* d_in, const int* in_sizes, int n_in,
                              void* d_out, int out_size)
{
    const float* x  = (const float*)d_in[0];
    const int*   ei = (const int*)d_in[1];      // JAX x64 disabled -> int32!
    const float* W  = (const float*)d_in[2];
    const float* a  = (const float*)d_in[3];
    float* out = (float*)d_out;

    const int N = in_sizes[0] / IN_F;        // 50000
    const int E = in_sizes[1] / 2;           // 1600000
    const int* src = ei;
    const int* dst = ei + E;

    float *h, *agg, *ssrc, *sdst, *rowsum;
    cudaGetSymbolAddress((void**)&h,      g_h);
    cudaGetSymbolAddress((void**)&agg,    g_agg);
    cudaGetSymbolAddress((void**)&ssrc,   g_ssrc);
    cudaGetSymbolAddress((void**)&sdst,   g_sdst);
    cudaGetSymbolAddress((void**)&rowsum, g_rowsum);

    cudaMemsetAsync(agg,    0, (size_t)N * OUT_F * sizeof(float), 0);
    cudaMemsetAsync(rowsum, 0, (size_t)N * sizeof(float), 0);

    // 1) h = x @ W
    gemm_kernel<<<(N + BM - 1) / BM, 256>>>(x, W, h, N);

    // 2) per-node scores
    score_kernel<<<(N + 7) / 8, 256>>>(h, a, ssrc, sdst, N);

    // 3) edge scatter (warp per edge)
    {
        const long long warps = E;
        const long long blocks = (warps * 32 + 255) / 256;
        edge_kernel<<<(unsigned)blocks, 256>>>(src, dst, h, ssrc, sdst, agg, rowsum, E);
    }

    // 4) finalize
    {
        const int total = N * OUT_F;
        finalize_kernel<<<(total + 255) / 256, 256>>>(agg, rowsum, out, total);
    }
}

// round 4
// speedup vs baseline: 1.0752x; 1.0752x over previous
#include <cuda_runtime.h>
#include <cuda_bf16.h>
#include <mma.h>
#include <math.h>

using namespace nvcuda;

#define N_NODES 50000
#define IN_F    256
#define OUT_F   128
#define ALPHA   0.2f
#define EPSV    1e-9f

// GEMM tiling
#define GBM 64
#define GBN 128
#define GBK 32
#define N_PAD 50048   // 782 blocks * 64 rows — padded so tail stores stay in-bounds

// ---------------- scratch (device globals; no allocations allowed) ----------
__device__ float g_h[(size_t)N_PAD * OUT_F];
__device__ float g_agg[(size_t)N_NODES * OUT_F];
__device__ float g_ssrc[N_NODES];
__device__ float g_sdst[N_NODES];
__device__ float g_rowsum[N_NODES];

// ---------------- GEMM: h = x @ W  (tf32 tensor cores) ----------------------
// 256 threads = 8 warps arranged 4(m) x 2(n); each warp: 16 rows x 64 cols
// = 4 wmma tiles of 16x16. K loop in chunks of 32 (4 k-steps of 8).
__global__ __launch_bounds__(256) void gemm_tf32_kernel(
    const float* __restrict__ x, const float* __restrict__ W,
    float* __restrict__ h, int N)
{
    __shared__ float As[GBM][GBK + 4];   // ldm 36 floats = 144B (16B aligned)
    __shared__ float Bs[GBK][GBN];       // ldm 128

    const int tid = threadIdx.x;
    const int wid = tid >> 5;
    const int wm = wid >> 1;     // 0..3
    const int wn = wid & 1;      // 0..1
    const int row0 = blockIdx.x * GBM;

    wmma::fragment<wmma::accumulator, 16, 16, 8, float> acc[4];
#pragma unroll
    for (int j = 0; j < 4; j++) wmma::fill_fragment(acc[j], 0.f);

    for (int k0 = 0; k0 < IN_F; k0 += GBK) {
        // As: 64x32 = 512 float4, 2 per thread. Clamp row for the tail block.
#pragma unroll
        for (int i = 0; i < 2; i++) {
            const int f = tid + i * 256;
            const int r = f >> 3;              // 8 float4 per row
            const int c = (f & 7) * 4;
            int grow = row0 + r; if (grow >= N) grow = N - 1;
            *reinterpret_cast<float4*>(&As[r][c]) =
                *reinterpret_cast<const float4*>(x + (size_t)grow * IN_F + k0 + c);
        }
        // Bs: 32x128 = 1024 float4, 4 per thread, coalesced.
#pragma unroll
        for (int i = 0; i < 4; i++) {
            const int f = tid + i * 256;
            const int r = f >> 5;              // 32 float4 per row
            const int c = (f & 31) * 4;
            *reinterpret_cast<float4*>(&Bs[r][c]) =
                *reinterpret_cast<const float4*>(W + (size_t)(k0 + r) * GBN + c);
        }
        __syncthreads();

#pragma unroll
        for (int ks = 0; ks < GBK; ks += 8) {
            wmma::fragment<wmma::matrix_a, 16, 16, 8, wmma::precision::tf32, wmma::row_major> af;
            wmma::load_matrix_sync(af, &As[wm * 16][ks], GBK + 4);
#pragma unroll
            for (int t = 0; t < af.num_elements; t++) af.x[t] = wmma::__float_to_tf32(af.x[t]);
#pragma unroll
            for (int j = 0; j < 4; j++) {
                wmma::fragment<wmma::matrix_b, 16, 16, 8, wmma::precision::tf32, wmma::row_major> bf;
                wmma::load_matrix_sync(bf, &Bs[ks][wn * 64 + j * 16], GBN);
#pragma unroll
                for (int t = 0; t < bf.num_elements; t++) bf.x[t] = wmma::__float_to_tf32(bf.x[t]);
                wmma::mma_sync(acc[j], af, bf, acc[j]);
            }
        }
        __syncthreads();
    }

#pragma unroll
    for (int j = 0; j < 4; j++)
        wmma::store_matrix_sync(h + (size_t)(row0 + wm * 16) * OUT_F + wn * 64 + j * 16,
                                acc[j], OUT_F, wmma::mem_row_major);
}

// ---------------- per-node scores: s_src[n] = h[n].a[:F], s_dst = h[n].a[F:] -
__global__ __launch_bounds__(256) void score_kernel(
    const float* __restrict__ h, const float* __restrict__ a,
    float* __restrict__ ssrc, float* __restrict__ sdst, int N)
{
    const int warp = (blockIdx.x * blockDim.x + threadIdx.x) >> 5;
    const int lane = threadIdx.x & 31;
    if (warp >= N) return;

    const float4 hv = reinterpret_cast<const float4*>(h + (size_t)warp * OUT_F)[lane];
    const float4 as = reinterpret_cast<const float4*>(a)[lane];
    const float4 ad = reinterpret_cast<const float4*>(a + OUT_F)[lane];

    float s1 = hv.x * as.x + hv.y * as.y + hv.z * as.z + hv.w * as.w;
    float s2 = hv.x * ad.x + hv.y * ad.y + hv.z * ad.z + hv.w * ad.w;
#pragma unroll
    for (int o = 16; o > 0; o >>= 1) {
        s1 += __shfl_xor_sync(0xFFFFFFFFu, s1, o);
        s2 += __shfl_xor_sync(0xFFFFFFFFu, s2, o);
    }
    if (lane == 0) { ssrc[warp] = s1; sdst[warp] = s2; }
}

// ---------------- edge scatter: warp per edge ---------------------------------
__device__ __forceinline__ void red_add_v4(float* addr, float4 v) {
    asm volatile("red.global.add.v4.f32 [%0], {%1, %2, %3, %4};"
                 :: "l"(addr), "f"(v.x), "f"(v.y), "f"(v.z), "f"(v.w)
                 : "memory");
}

__global__ __launch_bounds__(256) void edge_kernel(
    const int* __restrict__ src, const int* __restrict__ dst,
    const float* __restrict__ h,
    const float* __restrict__ ssrc, const float* __restrict__ sdst,
    float* __restrict__ agg, float* __restrict__ rowsum, int E)
{
    const int e = (int)((blockIdx.x * (unsigned)blockDim.x + threadIdx.x) >> 5);
    if (e >= E) return;
    const int lane = threadIdx.x & 31;

    const int s = src[e];
    const int d = dst[e];

    const float score = ssrc[s] + sdst[d];
    const float lr = score >= 0.f ? score : ALPHA * score;
    const float w = __expf(-lr);

    if (lane == 0) atomicAdd(&rowsum[s], w);

    const float4 hv = reinterpret_cast<const float4*>(h + (size_t)d * OUT_F)[lane];
    const float4 out = make_float4(hv.x * w, hv.y * w, hv.z * w, hv.w * w);
    red_add_v4(agg + (size_t)s * OUT_F + lane * 4, out);
}

// ---------------- finalize: out = elu(agg / (rowsum + eps)), float4 ----------
__global__ __launch_bounds__(256) void finalize_kernel(
    const float4* __restrict__ agg, const float* __restrict__ rowsum,
    float4* __restrict__ out, int total4)
{
    const int i = blockIdx.x * blockDim.x + threadIdx.x;
    if (i >= total4) return;
    const float4 v = agg[i];
    const float r = 1.f / (rowsum[i >> 5] + EPSV);   // 32 float4 per node row
    float a0 = v.x * r, a1 = v.y * r, a2 = v.z * r, a3 = v.w * r;
    a0 = a0 > 0.f ? a0 : expm1f(a0);
    a1 = a1 > 0.f ? a1 : expm1f(a1);
    a2 = a2 > 0.f ? a2 : expm1f(a2);
    a3 = a3 > 0.f ? a3 : expm1f(a3);
    out[i] = make_float4(a0, a1, a2, a3);
}

// ---------------- launch ------------------------------------------------------
extern "C" void kernel_launch(void* const* d_in, const int* in_sizes, int n_in,
                              void* d_out, int out_size)
{
    const float* x  = (const float*)d_in[0];
    const int*   ei = (const int*)d_in[1];      // JAX x64 disabled -> int32
    const float* W  = (const float*)d_in[2];
    const float* a  = (const float*)d_in[3];
    float* out = (float*)d_out;

    const int N = in_sizes[0] / IN_F;        // 50000
    const int E = in_sizes[1] / 2;           // 1600000
    const int* src = ei;
    const int* dst = ei + E;

    float *h, *agg, *ssrc, *sdst, *rowsum;
    cudaGetSymbolAddress((void**)&h,      g_h);
    cudaGetSymbolAddress((void**)&agg,    g_agg);
    cudaGetSymbolAddress((void**)&ssrc,   g_ssrc);
    cudaGetSymbolAddress((void**)&sdst,   g_sdst);
    cudaGetSymbolAddress((void**)&rowsum, g_rowsum);

    cudaMemsetAsync(agg,    0, (size_t)N * OUT_F * sizeof(float), 0);
    cudaMemsetAsync(rowsum, 0, (size_t)N * sizeof(float), 0);

    // 1) h = x @ W  (tf32 tensor cores)
    gemm_tf32_kernel<<<(N + GBM - 1) / GBM, 256>>>(x, W, h, N);

    // 2) per-node scores
    score_kernel<<<(N + 7) / 8, 256>>>(h, a, ssrc, sdst, N);

    // 3) edge scatter (warp per edge)
    {
        const long long warps = E;
        const long long blocks = (warps * 32 + 255) / 256;
        edge_kernel<<<(unsigned)blocks, 256>>>(src, dst, h, ssrc, sdst, agg, rowsum, E);
    }

    // 4) finalize (vectorized)
    {
        const int total4 = N * OUT_F / 4;
        finalize_kernel<<<(total4 + 255) / 256, 256>>>(
            (const float4*)agg, rowsum, (float4*)out, total4);
    }
}

// round 5
// speedup vs baseline: 1.3244x; 1.2318x over previous
#include <cuda_runtime.h>
#include <cuda_bf16.h>
#include <mma.h>
#include <math.h>

using namespace nvcuda;

#define N_NODES 50000
#define N_EDGES 1600000
#define IN_F    256
#define OUT_F   128
#define ALPHA   0.2f
#define EPSV    1e-9f

// GEMM tiling
#define GBM 64
#define GBN 128
#define GBK 32
#define N_PAD 50048   // 782 blocks * 64 rows — padded so tail stores stay in-bounds

// ---------------- scratch (device globals; no allocations allowed) ----------
__device__ float g_h[(size_t)N_PAD * OUT_F];
__device__ float g_ssrc[N_NODES];
__device__ float g_sdst[N_NODES];
__device__ int   g_deg[N_NODES];
__device__ int   g_off[N_NODES + 1];
__device__ int   g_cursor[N_NODES];
__device__ int   g_dsts[N_EDGES];
__device__ float g_ws[N_EDGES];

// ---------------- GEMM: h = x @ W  (tf32 tensor cores) ----------------------
__global__ __launch_bounds__(256) void gemm_tf32_kernel(
    const float* __restrict__ x, const float* __restrict__ W,
    float* __restrict__ h, int N)
{
    __shared__ float As[GBM][GBK + 4];
    __shared__ float Bs[GBK][GBN];

    const int tid = threadIdx.x;
    const int wid = tid >> 5;
    const int wm = wid >> 1;
    const int wn = wid & 1;
    const int row0 = blockIdx.x * GBM;

    wmma::fragment<wmma::accumulator, 16, 16, 8, float> acc[4];
#pragma unroll
    for (int j = 0; j < 4; j++) wmma::fill_fragment(acc[j], 0.f);

    for (int k0 = 0; k0 < IN_F; k0 += GBK) {
#pragma unroll
        for (int i = 0; i < 2; i++) {
            const int f = tid + i * 256;
            const int r = f >> 3;
            const int c = (f & 7) * 4;
            int grow = row0 + r; if (grow >= N) grow = N - 1;
            *reinterpret_cast<float4*>(&As[r][c]) =
                *reinterpret_cast<const float4*>(x + (size_t)grow * IN_F + k0 + c);
        }
#pragma unroll
        for (int i = 0; i < 4; i++) {
            const int f = tid + i * 256;
            const int r = f >> 5;
            const int c = (f & 31) * 4;
            *reinterpret_cast<float4*>(&Bs[r][c]) =
                *reinterpret_cast<const float4*>(W + (size_t)(k0 + r) * GBN + c);
        }
        __syncthreads();

#pragma unroll
        for (int ks = 0; ks < GBK; ks += 8) {
            wmma::fragment<wmma::matrix_a, 16, 16, 8, wmma::precision::tf32, wmma::row_major> af;
            wmma::load_matrix_sync(af, &As[wm * 16][ks], GBK + 4);
#pragma unroll
            for (int t = 0; t < af.num_elements; t++) af.x[t] = wmma::__float_to_tf32(af.x[t]);
#pragma unroll
            for (int j = 0; j < 4; j++) {
                wmma::fragment<wmma::matrix_b, 16, 16, 8, wmma::precision::tf32, wmma::row_major> bf;
                wmma::load_matrix_sync(bf, &Bs[ks][wn * 64 + j * 16], GBN);
#pragma unroll
                for (int t = 0; t < bf.num_elements; t++) bf.x[t] = wmma::__float_to_tf32(bf.x[t]);
                wmma::mma_sync(acc[j], af, bf, acc[j]);
            }
        }
        __syncthreads();
    }

#pragma unroll
    for (int j = 0; j < 4; j++)
        wmma::store_matrix_sync(h + (size_t)(row0 + wm * 16) * OUT_F + wn * 64 + j * 16,
                                acc[j], OUT_F, wmma::mem_row_major);
}

// ---------------- per-node scores -------------------------------------------
__global__ __launch_bounds__(256) void score_kernel(
    const float* __restrict__ h, const float* __restrict__ a,
    float* __restrict__ ssrc, float* __restrict__ sdst, int N)
{
    const int warp = (blockIdx.x * blockDim.x + threadIdx.x) >> 5;
    const int lane = threadIdx.x & 31;
    if (warp >= N) return;

    const float4 hv = reinterpret_cast<const float4*>(h + (size_t)warp * OUT_F)[lane];
    const float4 as = reinterpret_cast<const float4*>(a)[lane];
    const float4 ad = reinterpret_cast<const float4*>(a + OUT_F)[lane];

    float s1 = hv.x * as.x + hv.y * as.y + hv.z * as.z + hv.w * as.w;
    float s2 = hv.x * ad.x + hv.y * ad.y + hv.z * ad.z + hv.w * ad.w;
#pragma unroll
    for (int o = 16; o > 0; o >>= 1) {
        s1 += __shfl_xor_sync(0xFFFFFFFFu, s1, o);
        s2 += __shfl_xor_sync(0xFFFFFFFFu, s2, o);
    }
    if (lane == 0) { ssrc[warp] = s1; sdst[warp] = s2; }
}

// ---------------- CSR build: histogram --------------------------------------
__global__ __launch_bounds__(256) void hist_kernel(
    const int* __restrict__ src, int* __restrict__ deg, int E)
{
    const int e = blockIdx.x * blockDim.x + threadIdx.x;
    if (e < E) atomicAdd(&deg[src[e]], 1);
}

// ---------------- CSR build: prefix scan (single block, 1024 threads) -------
__global__ __launch_bounds__(1024) void scan_kernel(
    const int* __restrict__ deg, int* __restrict__ off,
    int* __restrict__ cursor, int N, int E)
{
    __shared__ int part[1024];
    const int t = threadIdx.x;
    const int CH = (N + 1023) / 1024;
    const int base = t * CH;

    int s = 0;
    for (int i = 0; i < CH; i++) {
        const int idx = base + i;
        if (idx < N) s += deg[idx];
    }
    part[t] = s;
    __syncthreads();

    // Hillis-Steele inclusive scan
    for (int o = 1; o < 1024; o <<= 1) {
        const int v = (t >= o) ? part[t - o] : 0;
        __syncthreads();
        part[t] += v;
        __syncthreads();
    }
    int run = (t == 0) ? 0 : part[t - 1];

    for (int i = 0; i < CH; i++) {
        const int idx = base + i;
        if (idx < N) {
            off[idx] = run;
            cursor[idx] = run;
            run += deg[idx];
        }
    }
    if (t == 1023) off[N] = E;
}

// ---------------- CSR build: scatter + edge weights --------------------------
__global__ __launch_bounds__(256) void scatter_kernel(
    const int* __restrict__ src, const int* __restrict__ dst,
    const float* __restrict__ ssrc, const float* __restrict__ sdst,
    int* __restrict__ cursor, int* __restrict__ dsts, float* __restrict__ ws,
    int E)
{
    const int e = blockIdx.x * blockDim.x + threadIdx.x;
    if (e >= E) return;
    const int s = src[e];
    const int d = dst[e];
    const float sc = ssrc[s] + sdst[d];
    const float lr = sc >= 0.f ? sc : ALPHA * sc;
    const float w = __expf(-lr);
    const int pos = atomicAdd(&cursor[s], 1);
    dsts[pos] = d;
    ws[pos] = w;
}

// ---------------- aggregate: warp per node, registers, fused elu -------------
__global__ __launch_bounds__(256) void aggregate_kernel(
    const float4* __restrict__ h4, const int* __restrict__ off,
    const int* __restrict__ dsts, const float* __restrict__ ws,
    float4* __restrict__ out4, int N)
{
    const int warp = (blockIdx.x * blockDim.x + threadIdx.x) >> 5;
    const int lane = threadIdx.x & 31;
    if (warp >= N) return;

    const int beg = off[warp];
    const int end = off[warp + 1];

    float ax = 0.f, ay = 0.f, az = 0.f, aw = 0.f, wsum = 0.f;

    int i = beg;
    for (; i + 2 <= end; i += 2) {
        const int d0 = dsts[i];
        const int d1 = dsts[i + 1];
        const float w0 = ws[i];
        const float w1 = ws[i + 1];
        const float4 v0 = h4[(size_t)d0 * 32 + lane];
        const float4 v1 = h4[(size_t)d1 * 32 + lane];
        ax = fmaf(w0, v0.x, fmaf(w1, v1.x, ax));
        ay = fmaf(w0, v0.y, fmaf(w1, v1.y, ay));
        az = fmaf(w0, v0.z, fmaf(w1, v1.z, az));
        aw = fmaf(w0, v0.w, fmaf(w1, v1.w, aw));
        wsum += w0 + w1;
    }
    if (i < end) {
        const int d0 = dsts[i];
        const float w0 = ws[i];
        const float4 v0 = h4[(size_t)d0 * 32 + lane];
        ax = fmaf(w0, v0.x, ax);
        ay = fmaf(w0, v0.y, ay);
        az = fmaf(w0, v0.z, az);
        aw = fmaf(w0, v0.w, aw);
        wsum += w0;
    }

    const float r = 1.f / (wsum + EPSV);
    ax *= r; ay *= r; az *= r; aw *= r;
    ax = ax > 0.f ? ax : expm1f(ax);
    ay = ay > 0.f ? ay : expm1f(ay);
    az = az > 0.f ? az : expm1f(az);
    aw = aw > 0.f ? aw : expm1f(aw);
    out4[(size_t)warp * 32 + lane] = make_float4(ax, ay, az, aw);
}

// ---------------- launch ------------------------------------------------------
extern "C" void kernel_launch(void* const* d_in, const int* in_sizes, int n_in,
                              void* d_out, int out_size)
{
    const float* x  = (const float*)d_in[0];
    const int*   ei = (const int*)d_in[1];      // JAX x64 disabled -> int32
    const float* W  = (const float*)d_in[2];
    const float* a  = (const float*)d_in[3];
    float* out = (float*)d_out;

    const int N = in_sizes[0] / IN_F;        // 50000
    const int E = in_sizes[1] / 2;           // 1600000
    const int* src = ei;
    const int* dst = ei + E;

    float *h, *ssrc, *sdst, *ws;
    int *deg, *off, *cursor, *dsts;
    cudaGetSymbolAddress((void**)&h,      g_h);
    cudaGetSymbolAddress((void**)&ssrc,   g_ssrc);
    cudaGetSymbolAddress((void**)&sdst,   g_sdst);
    cudaGetSymbolAddress((void**)&deg,    g_deg);
    cudaGetSymbolAddress((void**)&off,    g_off);
    cudaGetSymbolAddress((void**)&cursor, g_cursor);
    cudaGetSymbolAddress((void**)&dsts,   g_dsts);
    cudaGetSymbolAddress((void**)&ws,     g_ws);

    cudaMemsetAsync(deg, 0, (size_t)N * sizeof(int), 0);

    // CSR histogram (only needs src)
    hist_kernel<<<(E + 255) / 256, 256>>>(src, deg, E);

    // h = x @ W (tf32 tensor cores)
    gemm_tf32_kernel<<<(N + GBM - 1) / GBM, 256>>>(x, W, h, N);

    // per-node scores
    score_kernel<<<(N + 7) / 8, 256>>>(h, a, ssrc, sdst, N);

    // prefix scan -> offsets + cursors
    scan_kernel<<<1, 1024>>>(deg, off, cursor, N, E);

    // scatter edges into CSR order + precompute weights
    scatter_kernel<<<(E + 255) / 256, 256>>>(src, dst, ssrc, sdst, cursor, dsts, ws, E);

    // aggregate per node (atomic-free) + fused elu
    aggregate_kernel<<<(N * 32 + 255) / 256, 256>>>(
        (const float4*)h, off, dsts, ws, (float4*)out, N);
}